// round 1
// baseline (speedup 1.0000x reference)
#include <cuda_runtime.h>
#include <math.h>

#define NB   4
#define BSZ  8
#define NF   128
#define WDIM 512
#define IMG  256

// ---------------- scratch (static device globals; no allocation) -------------
__device__ float g_xa[BSZ * NF * IMG * IMG];          // 268 MB ping
__device__ float g_xb[BSZ * NF * IMG * IMG];          // 268 MB pong
__device__ float g_ws[BSZ * NF * NF * 9];             // per-sample modulated conv weights
__device__ float g_s[NB * BSZ * NF];                  // styles
__device__ float g_rgb[BSZ * (32*32 + 64*64 + 128*128 + 256*256)];  // native-res rgb

// ---------------- styles: s = w @ (to_style_w * cl)^T + b --------------------
__global__ void k_style(const float* __restrict__ w, const float* __restrict__ tsw,
                        const float* __restrict__ tsb) {
    int i = blockIdx.x / BSZ, b = blockIdx.x % BSZ;
    int c = threadIdx.x;                      // 128 threads
    __shared__ float sw[WDIM];
    for (int d = threadIdx.x; d < WDIM; d += blockDim.x)
        sw[d] = w[(i * BSZ + b) * WDIM + d];
    __syncthreads();
    const float* tw = tsw + (i * NF + c) * WDIM;
    float acc = 0.f;
    #pragma unroll 4
    for (int d = 0; d < WDIM; d++) acc += sw[d] * tw[d];
    const float cl = 0.044194173824159216f;   // 1/sqrt(512)
    g_s[(i * BSZ + b) * NF + c] = acc * cl + tsb[i * NF + c];
}

// ---------------- modulated + demodulated weights for conv (i, j) ------------
__global__ void k_modw(const float* __restrict__ conv_w, int i, int j) {
    int b = blockIdx.x / NF, co = blockIdx.x % NF;
    const float* wsrc = conv_w + (((size_t)(i * 2 + j) * NF + co) * NF) * 9;
    const float* s = g_s + (i * BSZ + b) * NF;
    const float c = 0.029462782549439483f;    // 1/sqrt(128*9)
    __shared__ float buf[NF * 9];
    __shared__ float red[32];
    float ss = 0.f;
    for (int t = threadIdx.x; t < NF * 9; t += blockDim.x) {
        float v = wsrc[t] * c * s[t / 9];
        buf[t] = v;
        ss += v * v;
    }
    for (int o = 16; o; o >>= 1) ss += __shfl_xor_sync(0xffffffffu, ss, o);
    if ((threadIdx.x & 31) == 0) red[threadIdx.x >> 5] = ss;
    __syncthreads();
    if (threadIdx.x < 32) {
        float v = (threadIdx.x < (blockDim.x >> 5)) ? red[threadIdx.x] : 0.f;
        for (int o = 16; o; o >>= 1) v += __shfl_xor_sync(0xffffffffu, v, o);
        if (threadIdx.x == 0) red[0] = v;
    }
    __syncthreads();
    float dem = rsqrtf(red[0] + 1e-8f);
    float* dst = g_ws + ((size_t)(b * NF) + co) * (NF * 9);
    for (int t = threadIdx.x; t < NF * 9; t += blockDim.x) dst[t] = buf[t] * dem;
}

// ---------------- initial constant: relu + broadcast over batch --------------
__global__ void k_init(const float* __restrict__ ic, float* __restrict__ x) {
    int idx = blockIdx.x * blockDim.x + threadIdx.x;          // over B*NF*32*32
    if (idx >= BSZ * NF * 32 * 32) return;
    int per = NF * 32 * 32;
    int r = idx % per;
    float v = ic[r];
    x[idx] = v > 0.f ? v : 0.f;
}

// ---------------- bilinear 2x upsample (half-pixel, clamped) -----------------
__global__ void k_up(const float* __restrict__ in, float* __restrict__ out, int rin) {
    int rout = rin * 2;
    int idx = blockIdx.x * blockDim.x + threadIdx.x;
    int total = BSZ * NF * rout * rout;
    if (idx >= total) return;
    int x = idx % rout;
    int t2 = idx / rout;
    int y = t2 % rout;
    int bc = t2 / rout;
    float fy = y * 0.5f - 0.25f, fx = x * 0.5f - 0.25f;
    int iy0 = (int)floorf(fy), ix0 = (int)floorf(fx);
    float ty = fy - iy0, tx = fx - ix0;
    int y0c = max(iy0, 0), y1c = min(iy0 + 1, rin - 1);
    int x0c = max(ix0, 0), x1c = min(ix0 + 1, rin - 1);
    const float* p = in + (size_t)bc * rin * rin;
    float v00 = p[y0c * rin + x0c], v01 = p[y0c * rin + x1c];
    float v10 = p[y1c * rin + x0c], v11 = p[y1c * rin + x1c];
    float v0 = v00 + tx * (v01 - v00);
    float v1 = v10 + tx * (v11 - v10);
    out[idx] = v0 + ty * (v1 - v0);
}

// ---------------- main modulated conv3x3 + noise + bias + leaky relu ---------
// CTA: 32x16 pixel tile, 32 output channels. 256 threads:
//   co_sub = t>>6 (4 groups of 8 co), pix = t&63: px=(pix&7)*4, py=(pix>>3)*2
// Each thread: 4x2 pixels x 8 co = 64 accumulators.
__global__ void __launch_bounds__(256, 2)
k_conv(const float* __restrict__ xin, float* __restrict__ xout,
       const float* __restrict__ noise, const float* __restrict__ sn_ptr,
       const float* __restrict__ bias, int r) {
    __shared__ float s_in[8][18][36];
    __shared__ float s_w[32][72];             // [co_local][ci*9+k]

    int bz = blockIdx.z;
    int b = bz >> 2, cg = bz & 3;
    int x0 = blockIdx.x * 32, y0 = blockIdx.y * 16;
    int t = threadIdx.x;
    int co_sub = t >> 6, pix = t & 63;
    int lx = (pix & 7) * 4, ly = (pix >> 3) * 2;
    int co0 = cg * 32;

    float acc[8][8];
    #pragma unroll
    for (int a = 0; a < 8; a++)
        #pragma unroll
        for (int p = 0; p < 8; p++) acc[a][p] = 0.f;

    const size_t ws_b = (size_t)b * NF * (NF * 9);

    for (int c0 = 0; c0 < NF; c0 += 8) {
        // ---- load weights: 32co x 8ci x 9
        {
            int co_l = t >> 3, ci_l = t & 7;
            const float* src = g_ws + ws_b + ((size_t)(co0 + co_l) * NF + (c0 + ci_l)) * 9;
            float* dst = &s_w[co_l][ci_l * 9];
            #pragma unroll
            for (int k = 0; k < 9; k++) dst[k] = src[k];
        }
        // ---- load input tile 8ci x 18 x 34 (zero padded)
        for (int e = t; e < 8 * 18 * 34; e += 256) {
            int ci_l = e / (18 * 34);
            int rem = e - ci_l * (18 * 34);
            int sy = rem / 34, sx = rem - sy * 34;
            int gy = y0 + sy - 1, gx = x0 + sx - 1;
            float v = 0.f;
            if (gy >= 0 && gy < r && gx >= 0 && gx < r)
                v = xin[(((size_t)(b * NF + c0 + ci_l)) * r + gy) * r + gx];
            s_in[ci_l][sy][sx] = v;
        }
        __syncthreads();

        #pragma unroll
        for (int ci = 0; ci < 8; ci++) {
            float in[4][6];
            #pragma unroll
            for (int dy = 0; dy < 4; dy++)
                #pragma unroll
                for (int dx = 0; dx < 6; dx++)
                    in[dy][dx] = s_in[ci][ly + dy][lx + dx];
            #pragma unroll
            for (int cl = 0; cl < 8; cl++) {
                const float* wp = &s_w[co_sub * 8 + cl][ci * 9];
                float w00 = wp[0], w01 = wp[1], w02 = wp[2];
                float w10 = wp[3], w11 = wp[4], w12 = wp[5];
                float w20 = wp[6], w21 = wp[7], w22 = wp[8];
                #pragma unroll
                for (int yy = 0; yy < 2; yy++)
                    #pragma unroll
                    for (int xx = 0; xx < 4; xx++) {
                        float a = acc[cl][yy * 4 + xx];
                        a += w00 * in[yy + 0][xx + 0];
                        a += w01 * in[yy + 0][xx + 1];
                        a += w02 * in[yy + 0][xx + 2];
                        a += w10 * in[yy + 1][xx + 0];
                        a += w11 * in[yy + 1][xx + 1];
                        a += w12 * in[yy + 1][xx + 2];
                        a += w20 * in[yy + 2][xx + 0];
                        a += w21 * in[yy + 2][xx + 1];
                        a += w22 * in[yy + 2][xx + 2];
                        acc[cl][yy * 4 + xx] = a;
                    }
            }
        }
        __syncthreads();
    }

    // ---- epilogue: noise + bias + leaky relu, store
    float sn = __ldg(sn_ptr);
    float nz[8];
    #pragma unroll
    for (int yy = 0; yy < 2; yy++)
        #pragma unroll
        for (int xx = 0; xx < 4; xx++) {
            int gy = y0 + ly + yy, gx = x0 + lx + xx;
            nz[yy * 4 + xx] = sn * noise[((size_t)b * r + gy) * r + gx];
        }
    #pragma unroll
    for (int cl = 0; cl < 8; cl++) {
        int co = co0 + co_sub * 8 + cl;
        float bb = bias[co];
        float* op = xout + ((size_t)(b * NF + co)) * r * r;
        #pragma unroll
        for (int yy = 0; yy < 2; yy++)
            #pragma unroll
            for (int xx = 0; xx < 4; xx++) {
                int gy = y0 + ly + yy, gx = x0 + lx + xx;
                float v = acc[cl][yy * 4 + xx] + nz[yy * 4 + xx] + bb;
                v = v > 0.f ? v : 0.2f * v;
                op[gy * r + gx] = v;
            }
    }
}

// ---------------- ToRGB: 1x1 modulated (no demod) conv to 1 channel ----------
__global__ void k_rgb(const float* __restrict__ xin, float* __restrict__ rgbout,
                      const float* __restrict__ rgb_w, int i, int r) {
    int b = blockIdx.y;
    __shared__ float wr[NF];
    if (threadIdx.x < NF) {
        const float cr = 0.08838834764831843f;  // 1/sqrt(128)
        wr[threadIdx.x] = rgb_w[i * NF + threadIdx.x] * cr * g_s[(i * BSZ + b) * NF + threadIdx.x];
    }
    __syncthreads();
    int p = blockIdx.x * blockDim.x + threadIdx.x;
    if (p >= r * r) return;
    const float* xp = xin + (size_t)b * NF * r * r + p;
    float acc = 0.f;
    #pragma unroll 4
    for (int ci = 0; ci < NF; ci++) acc += wr[ci] * xp[(size_t)ci * r * r];
    rgbout[(size_t)b * r * r + p] = acc;
}

// ---------------- final: sum of bilinearly-upsampled rgbs, /2 + 0.5 ----------
__global__ void k_final(float* __restrict__ out) {
    int idx = blockIdx.x * blockDim.x + threadIdx.x;
    if (idx >= BSZ * IMG * IMG) return;
    int b = idx / (IMG * IMG);
    int rem = idx - b * (IMG * IMG);
    int y = rem >> 8, x = rem & 255;
    float sum = 0.f;
    int roff = 0;
    #pragma unroll
    for (int i = 0; i < 4; i++) {
        int r = 32 << i;
        const float* src = g_rgb + (size_t)BSZ * roff + (size_t)b * r * r;
        float sc = (float)r * (1.f / 256.f);
        float fy = (y + 0.5f) * sc - 0.5f;
        float fx = (x + 0.5f) * sc - 0.5f;
        int iy0 = (int)floorf(fy), ix0 = (int)floorf(fx);
        float ty = fy - iy0, tx = fx - ix0;
        int y0c = max(iy0, 0), y1c = min(iy0 + 1, r - 1);
        int x0c = max(ix0, 0), x1c = min(ix0 + 1, r - 1);
        float v00 = src[y0c * r + x0c], v01 = src[y0c * r + x1c];
        float v10 = src[y1c * r + x0c], v11 = src[y1c * r + x1c];
        float v0 = v00 + tx * (v01 - v00);
        float v1 = v10 + tx * (v11 - v10);
        sum += v0 + ty * (v1 - v0);
        roff += r * r;
    }
    out[idx] = sum * 0.5f + 0.5f;
}

// =============================================================================
extern "C" void kernel_launch(void* const* d_in, const int* in_sizes, int n_in,
                              void* d_out, int out_size) {
    const float* w      = (const float*)d_in[0];
    const float* noise_in[4] = { (const float*)d_in[1], (const float*)d_in[2],
                                 (const float*)d_in[3], (const float*)d_in[4] };
    const float* ic     = (const float*)d_in[5];
    const float* tsw    = (const float*)d_in[6];
    const float* tsb    = (const float*)d_in[7];
    const float* conv_w = (const float*)d_in[8];
    const float* sn     = (const float*)d_in[9];
    const float* sbias  = (const float*)d_in[10];
    const float* rgb_w  = (const float*)d_in[11];
    float* out = (float*)d_out;

    float *xa, *xb, *rgb;
    cudaGetSymbolAddress((void**)&xa, g_xa);
    cudaGetSymbolAddress((void**)&xb, g_xb);
    cudaGetSymbolAddress((void**)&rgb, g_rgb);

    // styles for all blocks
    k_style<<<NB * BSZ, 128>>>(w, tsw, tsb);

    // initial x = relu(const) broadcast
    {
        int n = BSZ * NF * 32 * 32;
        k_init<<<(n + 255) / 256, 256>>>(ic, xa);
    }

    float* cur = xa;
    float* tmp = xb;
    int rgboff = 0;
    for (int i = 0; i < NB; i++) {
        int r = 32 << i;
        if (i > 0) {
            int n = BSZ * NF * r * r;
            k_up<<<(n + 255) / 256, 256>>>(cur, tmp, r / 2);
            float* t2 = cur; cur = tmp; tmp = t2;
        }
        for (int j = 0; j < 2; j++) {
            k_modw<<<BSZ * NF, 256>>>(conv_w, i, j);
            dim3 grid(r / 32, r / 16, BSZ * 4);
            k_conv<<<grid, 256>>>(cur, tmp,
                                  noise_in[i] + (size_t)j * BSZ * r * r,
                                  sn + (i * 2 + j),
                                  sbias + (i * 2 + j) * NF, r);
            float* t2 = cur; cur = tmp; tmp = t2;
        }
        dim3 rg((r * r + 255) / 256, BSZ);
        k_rgb<<<rg, 256>>>(cur, rgb + (size_t)BSZ * rgboff, rgb_w, i, r);
        rgboff += r * r;
    }

    {
        int n = BSZ * IMG * IMG;
        k_final<<<(n + 255) / 256, 256>>>(out);
    }
}